// round 1
// baseline (speedup 1.0000x reference)
#include <cuda_runtime.h>
#include <math_constants.h>

#define HW     576
#define CIN    512
#define NH     8
#define HD     64
#define NB     8
#define NTOK   2304      // V_NUM * HW
#define NPAIR  16        // groups(2) * heads(8)

// Scratch (device globals: allocation-free rule)
__device__ float g_q[NPAIR * HD * NTOK];   // [p][d][n]  (scale pre-applied)
__device__ float g_k[NPAIR * HD * NTOK];   // [p][d][n]
__device__ float g_v[NPAIR * NTOK * HD];   // [p][n][d]
__device__ float g_ao[NB * CIN * HW];      // attention out, [b][c][hw]

// ---------------------------------------------------------------------------
// Kernel A: QKV 1x1 conv.  qkv[b,o,hw] = sum_c x[b,c,hw] * w_qkv[o,c]
// Channel layout of the 1536 outputs: o = head*192 + which*64 + d
// (head-major, then q/k/v within head, per the reference reshape).
// Epilogue scatters into g_q/g_k/g_v.
// grid (9 hw-tiles, 24 o-tiles, 8 batches), 256 threads, 64x64 tile, BK=16.
// ---------------------------------------------------------------------------
__global__ __launch_bounds__(256) void qkv_kernel(const float* __restrict__ x,
                                                  const float* __restrict__ w) {
    __shared__ float sW[16][68];   // [c][o]  (padded: write conflicts -> 2-way)
    __shared__ float sX[16][64];   // [c][hw]
    const int tid = threadIdx.x;
    const int tx = tid & 15, ty = tid >> 4;
    const int hw0 = blockIdx.x * 64;
    const int o0  = blockIdx.y * 64;
    const int b   = blockIdx.z;
    const float* xb = x + b * (CIN * HW);

    float acc[4][4] = {};

    for (int k0 = 0; k0 < CIN; k0 += 16) {
#pragma unroll
        for (int r = 0; r < 4; r++) {
            int idx = tid + r * 256;
            int o_l = idx >> 4, c_l = idx & 15;
            sW[c_l][o_l] = w[(o0 + o_l) * CIN + k0 + c_l];
        }
#pragma unroll
        for (int r = 0; r < 4; r++) {
            int idx = tid + r * 256;
            int c_l = idx >> 6, hw_l = idx & 63;
            sX[c_l][hw_l] = xb[(k0 + c_l) * HW + hw0 + hw_l];
        }
        __syncthreads();
#pragma unroll
        for (int c = 0; c < 16; c++) {
            float4 wv = *(const float4*)&sW[c][ty * 4];
            float4 xv = *(const float4*)&sX[c][tx * 4];
            float aw[4] = {wv.x, wv.y, wv.z, wv.w};
            float ax[4] = {xv.x, xv.y, xv.z, xv.w};
#pragma unroll
            for (int i = 0; i < 4; i++)
#pragma unroll
                for (int j = 0; j < 4; j++)
                    acc[i][j] = fmaf(aw[i], ax[j], acc[i][j]);
        }
        __syncthreads();
    }

    // scatter epilogue
    const int g = b >> 2, v = b & 3;
    const float scale = 0.125f;   // hd^-0.5, folded into Q
#pragma unroll
    for (int i = 0; i < 4; i++) {
        int o = o0 + ty * 4 + i;
        int head = o / 192;
        int rem = o - head * 192;
        int which = rem >> 6;
        int d = rem & 63;
        int p = g * NH + head;
        int n_base = v * HW + hw0 + tx * 4;
        if (which == 0) {
            float4 val = make_float4(acc[i][0] * scale, acc[i][1] * scale,
                                     acc[i][2] * scale, acc[i][3] * scale);
            *(float4*)&g_q[(p * HD + d) * NTOK + n_base] = val;
        } else if (which == 1) {
            float4 val = make_float4(acc[i][0], acc[i][1], acc[i][2], acc[i][3]);
            *(float4*)&g_k[(p * HD + d) * NTOK + n_base] = val;
        } else {
#pragma unroll
            for (int j = 0; j < 4; j++)
                g_v[(p * NTOK + n_base + j) * HD + d] = acc[i][j];
        }
    }
}

// ---------------------------------------------------------------------------
// Kernel B: flash attention, fp32.
// grid (36 m-tiles, 16 pairs), 256 threads (16x16), BM=BN=64, hd=64.
// Output written directly in [b][c][hw] layout (g_ao).
// Dynamic smem: sQ/sK ([d][m|n]) + sV ([n][d]) + sP ([m][n]) = 64 KB.
// ---------------------------------------------------------------------------
__global__ __launch_bounds__(256) void flash_kernel() {
    extern __shared__ float sm[];
    float* sQ = sm;              // [64][64]  [d][m]
    float* sK = sm + 4096;       // [64][64]  [d][n]
    float* sV = sm + 8192;       // [64][64]  [n][d]
    float* sP = sm + 12288;      // [64][64]  [m][n]

    const int tid = threadIdx.x;
    const int tx = tid & 15, ty = tid >> 4;
    const int p = blockIdx.y;
    const int m0 = blockIdx.x * 64;

    // Load Q tile (coalesced: g_q is [p][d][n])
#pragma unroll
    for (int r = 0; r < 4; r++) {
        int idx4 = tid + r * 256;          // float4 index over 4096 floats
        int d = idx4 >> 4;
        int m4 = (idx4 & 15) * 4;
        *(float4*)&sQ[d * 64 + m4] =
            *(const float4*)&g_q[(p * HD + d) * NTOK + m0 + m4];
    }

    float rO[4][4] = {};
    float rM[4] = {-CUDART_INF_F, -CUDART_INF_F, -CUDART_INF_F, -CUDART_INF_F};
    float rL[4] = {};

    for (int n0 = 0; n0 < NTOK; n0 += 64) {
#pragma unroll
        for (int r = 0; r < 4; r++) {
            int idx4 = tid + r * 256;
            int row = idx4 >> 4;
            int c4 = (idx4 & 15) * 4;
            *(float4*)&sK[row * 64 + c4] =
                *(const float4*)&g_k[(p * HD + row) * NTOK + n0 + c4];
            *(float4*)&sV[row * 64 + c4] =
                *(const float4*)&g_v[(p * NTOK + n0 + row) * HD + c4];
        }
        __syncthreads();

        // S = Q^T K  (per thread: 4 m-rows x 4 n-cols)
        float S[4][4] = {};
#pragma unroll 16
        for (int d = 0; d < 64; d++) {
            float4 qv = *(const float4*)&sQ[d * 64 + ty * 4];
            float4 kv = *(const float4*)&sK[d * 64 + tx * 4];
            float aq[4] = {qv.x, qv.y, qv.z, qv.w};
            float ak[4] = {kv.x, kv.y, kv.z, kv.w};
#pragma unroll
            for (int i = 0; i < 4; i++)
#pragma unroll
                for (int j = 0; j < 4; j++)
                    S[i][j] = fmaf(aq[i], ak[j], S[i][j]);
        }

        // online softmax over n (shuffle all-reduce across 16 tx lanes)
#pragma unroll
        for (int i = 0; i < 4; i++) {
            float mx = fmaxf(fmaxf(S[i][0], S[i][1]), fmaxf(S[i][2], S[i][3]));
#pragma unroll
            for (int off = 1; off < 16; off <<= 1)
                mx = fmaxf(mx, __shfl_xor_sync(0xffffffffu, mx, off));
            float mnew = fmaxf(rM[i], mx);
            float alpha = __expf(rM[i] - mnew);
            rM[i] = mnew;
            float s = 0.f;
#pragma unroll
            for (int j = 0; j < 4; j++) {
                S[i][j] = __expf(S[i][j] - mnew);
                s += S[i][j];
            }
#pragma unroll
            for (int off = 1; off < 16; off <<= 1)
                s += __shfl_xor_sync(0xffffffffu, s, off);
            rL[i] = rL[i] * alpha + s;
#pragma unroll
            for (int j = 0; j < 4; j++) rO[i][j] *= alpha;
            *(float4*)&sP[(ty * 4 + i) * 64 + tx * 4] =
                make_float4(S[i][0], S[i][1], S[i][2], S[i][3]);
        }
        __syncthreads();

        // O += P @ V   (per thread: 4 m-rows x 4 d-cols)
#pragma unroll 16
        for (int n = 0; n < 64; n++) {
            float4 vv = *(const float4*)&sV[n * 64 + tx * 4];
            float av[4] = {vv.x, vv.y, vv.z, vv.w};
            float ap[4];
#pragma unroll
            for (int i = 0; i < 4; i++) ap[i] = sP[(ty * 4 + i) * 64 + n];
#pragma unroll
            for (int i = 0; i < 4; i++)
#pragma unroll
                for (int j = 0; j < 4; j++)
                    rO[i][j] = fmaf(ap[i], av[j], rO[i][j]);
        }
        __syncthreads();
    }

    // epilogue: normalize and write to [b][c][hw]
    float inv[4];
#pragma unroll
    for (int i = 0; i < 4; i++) inv[i] = 1.0f / rL[i];

    const int head = p & 7;
    const int v = m0 / HW;                 // m-tile never crosses a v boundary
    const int b = (p >> 3) * 4 + v;
    const int hwb = (m0 % HW) + ty * 4;    // 4 consecutive hw (i direction)
#pragma unroll
    for (int j = 0; j < 4; j++) {
        int c = head * HD + tx * 4 + j;
        float4 val = make_float4(rO[0][j] * inv[0], rO[1][j] * inv[1],
                                 rO[2][j] * inv[2], rO[3][j] * inv[3]);
        *(float4*)&g_ao[(b * CIN + c) * HW + hwb] = val;
    }
}

// ---------------------------------------------------------------------------
// Kernel C: proj 1x1 conv + bias.  out[b,o,hw] = sum_c g_ao[b,c,hw]*w[o,c] + bias[o]
// grid (9, 8, 8), 256 threads, 64x64 tile, BK=16.
// ---------------------------------------------------------------------------
__global__ __launch_bounds__(256) void proj_kernel(const float* __restrict__ w,
                                                   const float* __restrict__ bias,
                                                   float* __restrict__ out) {
    __shared__ float sW[16][68];
    __shared__ float sX[16][64];
    const int tid = threadIdx.x;
    const int tx = tid & 15, ty = tid >> 4;
    const int hw0 = blockIdx.x * 64;
    const int o0  = blockIdx.y * 64;
    const int b   = blockIdx.z;
    const float* xb = g_ao + b * (CIN * HW);

    float acc[4][4] = {};

    for (int k0 = 0; k0 < CIN; k0 += 16) {
#pragma unroll
        for (int r = 0; r < 4; r++) {
            int idx = tid + r * 256;
            int o_l = idx >> 4, c_l = idx & 15;
            sW[c_l][o_l] = w[(o0 + o_l) * CIN + k0 + c_l];
        }
#pragma unroll
        for (int r = 0; r < 4; r++) {
            int idx = tid + r * 256;
            int c_l = idx >> 6, hw_l = idx & 63;
            sX[c_l][hw_l] = xb[(k0 + c_l) * HW + hw0 + hw_l];
        }
        __syncthreads();
#pragma unroll
        for (int c = 0; c < 16; c++) {
            float4 wv = *(const float4*)&sW[c][ty * 4];
            float4 xv = *(const float4*)&sX[c][tx * 4];
            float aw[4] = {wv.x, wv.y, wv.z, wv.w};
            float ax[4] = {xv.x, xv.y, xv.z, xv.w};
#pragma unroll
            for (int i = 0; i < 4; i++)
#pragma unroll
                for (int j = 0; j < 4; j++)
                    acc[i][j] = fmaf(aw[i], ax[j], acc[i][j]);
        }
        __syncthreads();
    }

#pragma unroll
    for (int i = 0; i < 4; i++) {
        int o = o0 + ty * 4 + i;
        float bv = bias[o];
        float4 val = make_float4(acc[i][0] + bv, acc[i][1] + bv,
                                 acc[i][2] + bv, acc[i][3] + bv);
        *(float4*)&out[(b * CIN + o) * HW + hw0 + tx * 4] = val;
    }
}

// ---------------------------------------------------------------------------
extern "C" void kernel_launch(void* const* d_in, const int* in_sizes, int n_in,
                              void* d_out, int out_size) {
    const float* x      = (const float*)d_in[0];
    const float* w_qkv  = (const float*)d_in[1];
    const float* w_proj = (const float*)d_in[2];
    const float* b_proj = (const float*)d_in[3];
    float* out = (float*)d_out;

    cudaFuncSetAttribute(flash_kernel,
                         cudaFuncAttributeMaxDynamicSharedMemorySize, 65536);

    qkv_kernel<<<dim3(9, 24, 8), 256>>>(x, w_qkv);
    flash_kernel<<<dim3(36, 16), 256, 65536>>>();
    proj_kernel<<<dim3(9, 8, 8), 256>>>(w_proj, b_proj, out);
}

// round 2
// speedup vs baseline: 3.0395x; 3.0395x over previous
#include <cuda_runtime.h>
#include <math_constants.h>
#include <cstdint>

#define HW     576
#define CIN    512
#define HD     64
#define NTOK   2304      // V_NUM * HW
#define NPAIR  16        // groups(2) * heads(8)
#define NB     8

// Scratch (device globals: allocation-free rule). All tf32-rounded.
__device__ float g_q[NPAIR * NTOK * HD];   // [p][n][d], scale folded in
__device__ float g_k[NPAIR * NTOK * HD];   // [p][n][d]
__device__ float g_v[NPAIR * NTOK * HD];   // [p][n][d]
__device__ float g_ao[NB * CIN * HW];      // attention out, [b][c][hw] (fp32)

__device__ __forceinline__ uint32_t f2tf(float f) {
    uint32_t u; asm("cvt.rna.tf32.f32 %0, %1;" : "=r"(u) : "f"(f)); return u;
}

// D += A @ B, m16n8k8 tf32, fp32 accumulate (in place)
__device__ __forceinline__ void mma8(float* c, const uint32_t* a, uint32_t b0, uint32_t b1) {
    asm("mma.sync.aligned.m16n8k8.row.col.f32.tf32.tf32.f32 "
        "{%0,%1,%2,%3}, {%4,%5,%6,%7}, {%8,%9}, {%0,%1,%2,%3};\n"
        : "+f"(c[0]), "+f"(c[1]), "+f"(c[2]), "+f"(c[3])
        : "r"(a[0]), "r"(a[1]), "r"(a[2]), "r"(a[3]), "r"(b0), "r"(b1));
}

// ---------------------------------------------------------------------------
// Kernel A: QKV 1x1 conv via tf32 mma. Out[o][hw] = W[o][c] @ X[c][hw], per b.
// Block: 128(M=o) x 64(N=hw), BK=32, 8 warps (each warp: m16 strip, full N).
// Epilogue scatters tf32-rounded Q(scaled)/K/V into [p][n][d] layouts.
// grid (12, 9, 8), 256 threads.
// ---------------------------------------------------------------------------
__global__ __launch_bounds__(256) void qkv_mma(const float* __restrict__ x,
                                               const float* __restrict__ w) {
    __shared__ float sW[128 * 36];   // [m][k] pad 36 -> conflict-free A frags
    __shared__ float sX[32 * 72];    // [k][n] pad 72 -> conflict-free B frags
    const int tid = threadIdx.x;
    const int wp = tid >> 5, lane = tid & 31, r = lane >> 2, q = lane & 3;
    const int o0 = blockIdx.x * 128, hw0 = blockIdx.y * 64, b = blockIdx.z;
    const float* xb = x + b * (CIN * HW);

    float acc[8][4] = {};

    for (int k0 = 0; k0 < CIN; k0 += 32) {
#pragma unroll
        for (int rr = 0; rr < 4; rr++) {           // W tile 128x32
            int f = tid + rr * 256, row = f >> 3, c4 = (f & 7) * 4;
            float4 v = *(const float4*)&w[(o0 + row) * CIN + k0 + c4];
            sW[row * 36 + c4 + 0] = __uint_as_float(f2tf(v.x));
            sW[row * 36 + c4 + 1] = __uint_as_float(f2tf(v.y));
            sW[row * 36 + c4 + 2] = __uint_as_float(f2tf(v.z));
            sW[row * 36 + c4 + 3] = __uint_as_float(f2tf(v.w));
        }
#pragma unroll
        for (int rr = 0; rr < 2; rr++) {           // X tile 32x64
            int f = tid + rr * 256, c = f >> 4, h4 = (f & 15) * 4;
            float4 v = *(const float4*)&xb[(k0 + c) * HW + hw0 + h4];
            sX[c * 72 + h4 + 0] = __uint_as_float(f2tf(v.x));
            sX[c * 72 + h4 + 1] = __uint_as_float(f2tf(v.y));
            sX[c * 72 + h4 + 2] = __uint_as_float(f2tf(v.z));
            sX[c * 72 + h4 + 3] = __uint_as_float(f2tf(v.w));
        }
        __syncthreads();
#pragma unroll
        for (int s = 0; s < 4; s++) {
            uint32_t a[4];
            int m = wp * 16 + r;
            a[0] = __float_as_uint(sW[m * 36 + s * 8 + q]);
            a[1] = __float_as_uint(sW[(m + 8) * 36 + s * 8 + q]);
            a[2] = __float_as_uint(sW[m * 36 + s * 8 + q + 4]);
            a[3] = __float_as_uint(sW[(m + 8) * 36 + s * 8 + q + 4]);
#pragma unroll
            for (int nt = 0; nt < 8; nt++) {
                uint32_t b0 = __float_as_uint(sX[(s * 8 + q) * 72 + nt * 8 + r]);
                uint32_t b1 = __float_as_uint(sX[(s * 8 + q + 4) * 72 + nt * 8 + r]);
                mma8(acc[nt], a, b0, b1);
            }
        }
        __syncthreads();
    }

    // scatter epilogue: o -> (head, which, d); token n = v*576 + hw
    const int g = b >> 2, v = b & 3;
#pragma unroll
    for (int dd = 0; dd < 2; dd++) {
        int o = o0 + wp * 16 + r + dd * 8;
        int head = o / 192;
        int rem = o - head * 192;
        int which = rem >> 6;
        int d = rem & 63;
        float* dst = (which == 0) ? g_q : (which == 1) ? g_k : g_v;
        float sc = (which == 0) ? 0.125f : 1.0f;   // hd^-0.5 folded into Q
        int p = g * 8 + head;
        int pbase = p * NTOK;
#pragma unroll
        for (int nt = 0; nt < 8; nt++) {
            int n = v * HW + hw0 + nt * 8 + 2 * q;
            dst[(pbase + n) * HD + d]       = __uint_as_float(f2tf(acc[nt][dd * 2 + 0] * sc));
            dst[(pbase + n + 1) * HD + d]   = __uint_as_float(f2tf(acc[nt][dd * 2 + 1] * sc));
        }
    }
}

// ---------------------------------------------------------------------------
// Kernel B: flash attention, tf32 mma. grid (36 m-tiles of 64, 16 pairs),
// 128 threads (4 warps, each owns an m16 strip). Q frags register-resident.
// smem: sQP (Q tile, reused as P) 64x68 | sK 64x68 | sV 64x72 = 53248 B.
// ---------------------------------------------------------------------------
__global__ __launch_bounds__(128, 3) void flash_mma() {
    extern __shared__ float sm[];
    float* sQP = sm;               // [m][d] pad 68, later [m][n] P buffer
    float* sK  = sm + 64 * 68;     // [n][d] pad 68
    float* sV  = sm + 2 * 64 * 68; // [n][d] pad 72

    const int tid = threadIdx.x, wp = tid >> 5, lane = tid & 31;
    const int r = lane >> 2, q = lane & 3;
    const int p = blockIdx.y, m0 = blockIdx.x * 64;
    const int w16 = wp * 16;

    const float* Qb = g_q + (p * NTOK + m0) * HD;
    const float* Kb = g_k + p * NTOK * HD;
    const float* Vb = g_v + p * NTOK * HD;

    // stage Q tile, then fragments -> registers for the whole kernel
#pragma unroll
    for (int rr = 0; rr < 8; rr++) {
        int f = tid + rr * 128, row = f >> 4, d4 = (f & 15) * 4;
        *(float4*)&sQP[row * 68 + d4] = *(const float4*)&Qb[row * HD + d4];
    }
    __syncthreads();
    uint32_t qf[8][4];
#pragma unroll
    for (int s = 0; s < 8; s++) {
        qf[s][0] = __float_as_uint(sQP[(w16 + r) * 68 + s * 8 + q]);
        qf[s][1] = __float_as_uint(sQP[(w16 + r + 8) * 68 + s * 8 + q]);
        qf[s][2] = __float_as_uint(sQP[(w16 + r) * 68 + s * 8 + q + 4]);
        qf[s][3] = __float_as_uint(sQP[(w16 + r + 8) * 68 + s * 8 + q + 4]);
    }
    __syncthreads();

    float rO[8][4] = {};
    float rM0 = -CUDART_INF_F, rM1 = -CUDART_INF_F, rL0 = 0.f, rL1 = 0.f;

    for (int n0 = 0; n0 < NTOK; n0 += 64) {
#pragma unroll
        for (int rr = 0; rr < 8; rr++) {
            int f = tid + rr * 128, row = f >> 4, d4 = (f & 15) * 4;
            *(float4*)&sK[row * 68 + d4] = *(const float4*)&Kb[(n0 + row) * HD + d4];
            *(float4*)&sV[row * 72 + d4] = *(const float4*)&Vb[(n0 + row) * HD + d4];
        }
        __syncthreads();

        // S(m16 x n64) = Q K^T
        float S[8][4] = {};
#pragma unroll
        for (int s = 0; s < 8; s++)
#pragma unroll
            for (int nt = 0; nt < 8; nt++) {
                uint32_t b0 = __float_as_uint(sK[(nt * 8 + r) * 68 + s * 8 + q]);
                uint32_t b1 = __float_as_uint(sK[(nt * 8 + r) * 68 + s * 8 + q + 4]);
                mma8(S[nt], qf[s], b0, b1);
            }

        // online softmax; thread owns rows (r) via regs 0,1 and (r+8) via 2,3
        float mx0 = -CUDART_INF_F, mx1 = -CUDART_INF_F;
#pragma unroll
        for (int nt = 0; nt < 8; nt++) {
            mx0 = fmaxf(mx0, fmaxf(S[nt][0], S[nt][1]));
            mx1 = fmaxf(mx1, fmaxf(S[nt][2], S[nt][3]));
        }
        mx0 = fmaxf(mx0, __shfl_xor_sync(0xffffffffu, mx0, 1));
        mx0 = fmaxf(mx0, __shfl_xor_sync(0xffffffffu, mx0, 2));
        mx1 = fmaxf(mx1, __shfl_xor_sync(0xffffffffu, mx1, 1));
        mx1 = fmaxf(mx1, __shfl_xor_sync(0xffffffffu, mx1, 2));
        float mn0 = fmaxf(rM0, mx0), mn1 = fmaxf(rM1, mx1);
        float al0 = __expf(rM0 - mn0), al1 = __expf(rM1 - mn1);
        rM0 = mn0; rM1 = mn1;

        float sum0 = 0.f, sum1 = 0.f;
#pragma unroll
        for (int nt = 0; nt < 8; nt++) {
            float e0 = __expf(S[nt][0] - mn0), e1 = __expf(S[nt][1] - mn0);
            float e2 = __expf(S[nt][2] - mn1), e3 = __expf(S[nt][3] - mn1);
            sum0 += e0 + e1; sum1 += e2 + e3;
            sQP[(w16 + r) * 68 + nt * 8 + 2 * q]         = __uint_as_float(f2tf(e0));
            sQP[(w16 + r) * 68 + nt * 8 + 2 * q + 1]     = __uint_as_float(f2tf(e1));
            sQP[(w16 + r + 8) * 68 + nt * 8 + 2 * q]     = __uint_as_float(f2tf(e2));
            sQP[(w16 + r + 8) * 68 + nt * 8 + 2 * q + 1] = __uint_as_float(f2tf(e3));
        }
        sum0 += __shfl_xor_sync(0xffffffffu, sum0, 1);
        sum0 += __shfl_xor_sync(0xffffffffu, sum0, 2);
        sum1 += __shfl_xor_sync(0xffffffffu, sum1, 1);
        sum1 += __shfl_xor_sync(0xffffffffu, sum1, 2);
        rL0 = rL0 * al0 + sum0;
        rL1 = rL1 * al1 + sum1;
#pragma unroll
        for (int dt = 0; dt < 8; dt++) {
            rO[dt][0] *= al0; rO[dt][1] *= al0;
            rO[dt][2] *= al1; rO[dt][3] *= al1;
        }
        __syncwarp();   // P rows are warp-private; make writes visible

        // O(m16 x d64) += P @ V
#pragma unroll
        for (int s = 0; s < 8; s++) {
            uint32_t a[4];
            a[0] = __float_as_uint(sQP[(w16 + r) * 68 + s * 8 + q]);
            a[1] = __float_as_uint(sQP[(w16 + r + 8) * 68 + s * 8 + q]);
            a[2] = __float_as_uint(sQP[(w16 + r) * 68 + s * 8 + q + 4]);
            a[3] = __float_as_uint(sQP[(w16 + r + 8) * 68 + s * 8 + q + 4]);
#pragma unroll
            for (int dt = 0; dt < 8; dt++) {
                uint32_t b0 = __float_as_uint(sV[(s * 8 + q) * 72 + dt * 8 + r]);
                uint32_t b1 = __float_as_uint(sV[(s * 8 + q + 4) * 72 + dt * 8 + r]);
                mma8(rO[dt], a, b0, b1);
            }
        }
        __syncthreads();
    }

    // epilogue: normalize, write [b][c][hw]. 64-tile never crosses a v boundary.
    float i0 = 1.f / rL0, i1 = 1.f / rL1;
    const int head = p & 7, gi = p >> 3;
    const int v = m0 / HW;
    const int bb = gi * 4 + v;
    const int hwb = m0 - v * HW + w16 + r;
#pragma unroll
    for (int dt = 0; dt < 8; dt++) {
        int c = head * 64 + dt * 8 + 2 * q;
        g_ao[(bb * CIN + c) * HW + hwb]         = rO[dt][0] * i0;
        g_ao[(bb * CIN + c + 1) * HW + hwb]     = rO[dt][1] * i0;
        g_ao[(bb * CIN + c) * HW + hwb + 8]     = rO[dt][2] * i1;
        g_ao[(bb * CIN + c + 1) * HW + hwb + 8] = rO[dt][3] * i1;
    }
}

// ---------------------------------------------------------------------------
// Kernel C: proj 1x1 conv + bias via tf32 mma. grid (4, 9, 8), 256 threads.
// ---------------------------------------------------------------------------
__global__ __launch_bounds__(256) void proj_mma(const float* __restrict__ w,
                                                const float* __restrict__ bias,
                                                float* __restrict__ out) {
    __shared__ float sW[128 * 36];
    __shared__ float sX[32 * 72];
    const int tid = threadIdx.x;
    const int wp = tid >> 5, lane = tid & 31, r = lane >> 2, q = lane & 3;
    const int o0 = blockIdx.x * 128, hw0 = blockIdx.y * 64, b = blockIdx.z;
    const float* xb = g_ao + b * (CIN * HW);

    float acc[8][4] = {};

    for (int k0 = 0; k0 < CIN; k0 += 32) {
#pragma unroll
        for (int rr = 0; rr < 4; rr++) {
            int f = tid + rr * 256, row = f >> 3, c4 = (f & 7) * 4;
            float4 v = *(const float4*)&w[(o0 + row) * CIN + k0 + c4];
            sW[row * 36 + c4 + 0] = __uint_as_float(f2tf(v.x));
            sW[row * 36 + c4 + 1] = __uint_as_float(f2tf(v.y));
            sW[row * 36 + c4 + 2] = __uint_as_float(f2tf(v.z));
            sW[row * 36 + c4 + 3] = __uint_as_float(f2tf(v.w));
        }
#pragma unroll
        for (int rr = 0; rr < 2; rr++) {
            int f = tid + rr * 256, c = f >> 4, h4 = (f & 15) * 4;
            float4 v = *(const float4*)&xb[(k0 + c) * HW + hw0 + h4];
            sX[c * 72 + h4 + 0] = __uint_as_float(f2tf(v.x));
            sX[c * 72 + h4 + 1] = __uint_as_float(f2tf(v.y));
            sX[c * 72 + h4 + 2] = __uint_as_float(f2tf(v.z));
            sX[c * 72 + h4 + 3] = __uint_as_float(f2tf(v.w));
        }
        __syncthreads();
#pragma unroll
        for (int s = 0; s < 4; s++) {
            uint32_t a[4];
            int m = wp * 16 + r;
            a[0] = __float_as_uint(sW[m * 36 + s * 8 + q]);
            a[1] = __float_as_uint(sW[(m + 8) * 36 + s * 8 + q]);
            a[2] = __float_as_uint(sW[m * 36 + s * 8 + q + 4]);
            a[3] = __float_as_uint(sW[(m + 8) * 36 + s * 8 + q + 4]);
#pragma unroll
            for (int nt = 0; nt < 8; nt++) {
                uint32_t b0 = __float_as_uint(sX[(s * 8 + q) * 72 + nt * 8 + r]);
                uint32_t b1 = __float_as_uint(sX[(s * 8 + q + 4) * 72 + nt * 8 + r]);
                mma8(acc[nt], a, b0, b1);
            }
        }
        __syncthreads();
    }

#pragma unroll
    for (int dd = 0; dd < 2; dd++) {
        int o = o0 + wp * 16 + r + dd * 8;
        float bv = bias[o];
#pragma unroll
        for (int nt = 0; nt < 8; nt++) {
            int hw = hw0 + nt * 8 + 2 * q;
            float2 val = make_float2(acc[nt][dd * 2 + 0] + bv,
                                     acc[nt][dd * 2 + 1] + bv);
            *(float2*)&out[(b * CIN + o) * HW + hw] = val;
        }
    }
}

// ---------------------------------------------------------------------------
extern "C" void kernel_launch(void* const* d_in, const int* in_sizes, int n_in,
                              void* d_out, int out_size) {
    const float* x      = (const float*)d_in[0];
    const float* w_qkv  = (const float*)d_in[1];
    const float* w_proj = (const float*)d_in[2];
    const float* b_proj = (const float*)d_in[3];
    float* out = (float*)d_out;

    cudaFuncSetAttribute(flash_mma,
                         cudaFuncAttributeMaxDynamicSharedMemorySize, 53248);

    qkv_mma<<<dim3(12, 9, 8), 256>>>(x, w_qkv);
    flash_mma<<<dim3(36, 16), 128, 53248>>>();
    proj_mma<<<dim3(4, 9, 8), 256>>>(w_proj, b_proj, out);
}

// round 3
// speedup vs baseline: 3.8620x; 1.2706x over previous
#include <cuda_runtime.h>
#include <math_constants.h>
#include <cstdint>

#define HW     576
#define CIN    512
#define HD     64
#define NTOK   2304      // V_NUM * HW
#define NPAIR  16        // groups(2) * heads(8)
#define NB     8
#define QSCALE (0.125f * 1.4426950408889634f)   // hd^-0.5 * log2(e)

// Scratch (device globals: allocation-free rule). All tf32-rounded.
__device__ __align__(16) float g_q[NPAIR * NTOK * HD];   // [p][n][d], scale folded
__device__ __align__(16) float g_k[NPAIR * NTOK * HD];   // [p][n][d]
__device__ __align__(16) float g_v[NPAIR * HD * NTOK];   // [p][d][n]
__device__ __align__(16) float g_ao[NB * HW * CIN];      // attn out, [b][hw][c], tf32
__device__ __align__(16) float g_xr[NB * CIN * HW];      // tf32 x
__device__ __align__(16) float g_wqr[3 * CIN * CIN];     // tf32 w_qkv
__device__ __align__(16) float g_wpr[CIN * CIN];         // tf32 w_proj

// ---------------- helpers ----------------
__device__ __forceinline__ float tfr(float f) {
    uint32_t u; asm("cvt.rna.tf32.f32 %0, %1;" : "=r"(u) : "f"(f));
    return __uint_as_float(u);
}
__device__ __forceinline__ void mma8(float* c, const uint32_t* a, uint32_t b0, uint32_t b1) {
    asm("mma.sync.aligned.m16n8k8.row.col.f32.tf32.tf32.f32 "
        "{%0,%1,%2,%3}, {%4,%5,%6,%7}, {%8,%9}, {%0,%1,%2,%3};\n"
        : "+f"(c[0]), "+f"(c[1]), "+f"(c[2]), "+f"(c[3])
        : "r"(a[0]), "r"(a[1]), "r"(a[2]), "r"(a[3]), "r"(b0), "r"(b1));
}
__device__ __forceinline__ void ldsm4(uint32_t* d, uint32_t a) {
    asm volatile("ldmatrix.sync.aligned.m8n8.x4.shared.b16 {%0,%1,%2,%3}, [%4];\n"
        : "=r"(d[0]), "=r"(d[1]), "=r"(d[2]), "=r"(d[3]) : "r"(a));
}
__device__ __forceinline__ uint32_t s2u(const void* p) {
    return (uint32_t)__cvta_generic_to_shared(p);
}
__device__ __forceinline__ void cpa16(uint32_t dst, const void* src) {
    asm volatile("cp.async.cg.shared.global [%0], [%1], 16;\n" :: "r"(dst), "l"(src));
}
__device__ __forceinline__ void cpa4(uint32_t dst, const void* src) {
    asm volatile("cp.async.ca.shared.global [%0], [%1], 4;\n" :: "r"(dst), "l"(src));
}
__device__ __forceinline__ void cpcommit() {
    asm volatile("cp.async.commit_group;\n" ::: "memory");
}
__device__ __forceinline__ void cpwait0() {
    asm volatile("cp.async.wait_group 0;\n" ::: "memory");
}
__device__ __forceinline__ void cpwait1() {
    asm volatile("cp.async.wait_group 1;\n" ::: "memory");
}

// LDSM lane address offsets (bytes), row stride in floats as parameter.
// A-fragment tiles: {rows 0-7,c0-3}{rows 8-15,c0-3}{rows 0-7,c4-7}{rows 8-15,c4-7}
__device__ __forceinline__ uint32_t a_off(int lane, int stride) {
    return (uint32_t)(((lane & 7) + ((lane >> 3) & 1) * 8) * stride * 4 + (lane >> 4) * 16);
}
// B-fragment x4 tiles: {nt,h0}{nt,h1}{nt+1,h0}{nt+1,h1}
__device__ __forceinline__ uint32_t b_off(int lane, int stride) {
    return (uint32_t)(((((lane >> 4) & 1) * 8 + (lane & 7)) * stride) * 4 + ((lane >> 3) & 1) * 16);
}

// ---------------------------------------------------------------------------
// Prologue: tf32-round x, w_qkv, w_proj once.
// ---------------------------------------------------------------------------
__global__ __launch_bounds__(256) void cvt_k(const float4* __restrict__ x,
                                             const float4* __restrict__ wq,
                                             const float4* __restrict__ wp) {
    int i = blockIdx.x * 256 + threadIdx.x;
    float4 v; float4* dst;
    if (i < 589824)       { v = x[i];           dst = (float4*)g_xr  + i; }
    else if (i < 786432)  { v = wq[i - 589824]; dst = (float4*)g_wqr + (i - 589824); }
    else                  { v = wp[i - 786432]; dst = (float4*)g_wpr + (i - 786432); }
    *dst = make_float4(tfr(v.x), tfr(v.y), tfr(v.z), tfr(v.w));
}

// ---------------------------------------------------------------------------
// Kernel A: QKV 1x1 conv. D[o][hw] = W[o][c] @ X[c][hw], per batch.
// 256 thr (8 warps x m16), M=128(o) x N=64(hw), BK=32, double-buffered cp.async.
// sW [128][36] (A, LDSM), sX [64 hw][36 c] (B, LDSM; transposed scalar g2s).
// ---------------------------------------------------------------------------
__global__ __launch_bounds__(256, 3) void qkv_mma() {
    extern __shared__ float sm[];
    float* sW = sm;                 // 2 x 128*36
    float* sX = sm + 2 * 128 * 36;  // 2 x 64*36
    const int tid = threadIdx.x, wp = tid >> 5, lane = tid & 31;
    const int r = lane >> 2, q = lane & 3, w16 = wp * 16;
    const int o0 = blockIdx.x * 128, hw0 = blockIdx.y * 64, b = blockIdx.z;
    const float* xb = g_xr + b * (CIN * HW);

    const uint32_t sWb = s2u(sW), sXb = s2u(sX);
    const uint32_t aof = a_off(lane, 36), bof = b_off(lane, 36);

#define QKV_PF(K0, BUF) {                                                        \
    _Pragma("unroll") for (int rr = 0; rr < 4; rr++) {                           \
        int f = tid + rr * 256, row = f >> 3, c4 = (f & 7) * 4;                  \
        cpa16(sWb + (uint32_t)((BUF) * 4608 + row * 36 + c4) * 4u,               \
              &g_wqr[(o0 + row) * CIN + (K0) + c4]);                             \
    }                                                                            \
    _Pragma("unroll") for (int rr = 0; rr < 8; rr++) {                           \
        int f = tid + rr * 256, c = f >> 6, hh = f & 63;                         \
        cpa4(sXb + (uint32_t)((BUF) * 2304 + hh * 36 + c) * 4u,                  \
             &xb[((K0) + c) * HW + hw0 + hh]);                                   \
    }                                                                            \
    cpcommit(); }

    QKV_PF(0, 0);
    float acc[8][4] = {};

    for (int kk = 0; kk < 16; kk++) {
        int buf = kk & 1;
        cpwait0();
        __syncthreads();
        if (kk + 1 < 16) QKV_PF((kk + 1) * 32, buf ^ 1);

        uint32_t wadr = sWb + (uint32_t)(buf * 4608 + w16 * 36) * 4u + aof;
        uint32_t xadr = sXb + (uint32_t)(buf * 2304) * 4u + bof;
#pragma unroll
        for (int s = 0; s < 4; s++) {
            uint32_t a[4]; ldsm4(a, wadr + s * 32);
#pragma unroll
            for (int j = 0; j < 4; j++) {
                uint32_t bb[4]; ldsm4(bb, xadr + (uint32_t)(j * 16 * 36) * 4u + s * 32);
                mma8(acc[2 * j], a, bb[0], bb[1]);
                mma8(acc[2 * j + 1], a, bb[2], bb[3]);
            }
        }
        __syncthreads();
    }

    // scatter epilogue: o = head*192 + which*64 + d ; token n = v*HW + hw
    const int g2 = b >> 2, vv = b & 3;
#pragma unroll
    for (int dd = 0; dd < 2; dd++) {
        int o = o0 + w16 + r + dd * 8;
        int head = o / 192, rem = o - head * 192, which = rem >> 6, d = rem & 63;
        int pp = g2 * 8 + head;
        if (which == 0) {
#pragma unroll
            for (int nt = 0; nt < 8; nt++) {
                int n = vv * HW + hw0 + nt * 8 + 2 * q;
                g_q[(pp * NTOK + n) * HD + d]     = tfr(acc[nt][dd * 2 + 0] * QSCALE);
                g_q[(pp * NTOK + n + 1) * HD + d] = tfr(acc[nt][dd * 2 + 1] * QSCALE);
            }
        } else if (which == 1) {
#pragma unroll
            for (int nt = 0; nt < 8; nt++) {
                int n = vv * HW + hw0 + nt * 8 + 2 * q;
                g_k[(pp * NTOK + n) * HD + d]     = tfr(acc[nt][dd * 2 + 0]);
                g_k[(pp * NTOK + n + 1) * HD + d] = tfr(acc[nt][dd * 2 + 1]);
            }
        } else {
#pragma unroll
            for (int nt = 0; nt < 8; nt++) {
                int n = vv * HW + hw0 + nt * 8 + 2 * q;
                *(float2*)&g_v[(pp * HD + d) * NTOK + n] =
                    make_float2(tfr(acc[nt][dd * 2 + 0]), tfr(acc[nt][dd * 2 + 1]));
            }
        }
    }
}

// ---------------------------------------------------------------------------
// Kernel B: flash attention, tf32 mma + LDSM, max-free base-2 softmax.
// grid (18, 16), 256 thr (8 warps x m16 strips), BM=128, BN=64.
// smem: sP [128][68] (Q staging, then P) | sK 2x[64 n][68 d] | sV 2x[64 d][68 n].
// Double-buffered cp.async K/V.
// ---------------------------------------------------------------------------
__global__ __launch_bounds__(256, 2) void flash_mma() {
    extern __shared__ float sm[];
    float* sP = sm;                                  // 128*68
    const uint32_t sPb = s2u(sP);
    const uint32_t sKb = sPb + 128 * 68 * 4;         // 2 x 64*68
    const uint32_t sVb = sKb + 2 * 64 * 68 * 4;      // 2 x 64*68

    const int tid = threadIdx.x, wp = tid >> 5, lane = tid & 31;
    const int r = lane >> 2, q = lane & 3, w16 = wp * 16;
    const int p = blockIdx.y, m0 = blockIdx.x * 128;

    const float* Qb = g_q + (p * NTOK + m0) * HD;
    const float* Kb = g_k + p * NTOK * HD;
    const float* Vb = g_v + p * HD * NTOK;

    const uint32_t aof = a_off(lane, 68), bof = b_off(lane, 68);

#define FL_PF(N0, BUF) {                                                         \
    _Pragma("unroll") for (int rr = 0; rr < 4; rr++) {                           \
        int f = tid + rr * 256, row = f >> 4, c4 = (f & 15) * 4;                 \
        cpa16(sKb + (uint32_t)((BUF) * 4352 + row * 68 + c4) * 4u,               \
              Kb + ((N0) + row) * HD + c4);                                      \
        cpa16(sVb + (uint32_t)((BUF) * 4352 + row * 68 + c4) * 4u,               \
              Vb + row * NTOK + (N0) + c4);                                      \
    }                                                                            \
    cpcommit(); }

    // stage Q (group), then first K/V (group)
#pragma unroll
    for (int rr = 0; rr < 8; rr++) {
        int f = tid + rr * 256, row = f >> 4, c4 = (f & 15) * 4;
        cpa16(sPb + (uint32_t)(row * 68 + c4) * 4u, Qb + row * HD + c4);
    }
    cpcommit();
    FL_PF(0, 0);

    cpwait1();           // Q ready
    __syncthreads();
    uint32_t qf[8][4];
    {
        uint32_t qadr = sPb + (uint32_t)(w16 * 68) * 4u + aof;
#pragma unroll
        for (int s = 0; s < 8; s++) ldsm4(qf[s], qadr + s * 32);
    }

    float rO[8][4] = {};
    float l0 = 0.f, l1 = 0.f;

    for (int it = 0; it < 36; it++) {
        const int buf = it & 1;
        cpwait0();
        __syncthreads();
        if (it + 1 < 36) FL_PF((it + 1) * 64, buf ^ 1);

        // S(m16 x n64) = Q K^T (base-2-scaled; scale folded into Q)
        float S[8][4] = {};
        {
            uint32_t kadr = sKb + (uint32_t)(buf * 4352) * 4u + bof;
#pragma unroll
            for (int s = 0; s < 8; s++) {
#pragma unroll
                for (int j = 0; j < 4; j++) {
                    uint32_t bb[4]; ldsm4(bb, kadr + (uint32_t)(j * 16 * 68) * 4u + s * 32);
                    mma8(S[2 * j], qf[s], bb[0], bb[1]);
                    mma8(S[2 * j + 1], qf[s], bb[2], bb[3]);
                }
            }
        }

        // max-free softmax: p = exp2(S); accumulate row sums
        float sum0 = 0.f, sum1 = 0.f;
#pragma unroll
        for (int nt = 0; nt < 8; nt++) {
            float e0 = exp2f(S[nt][0]), e1 = exp2f(S[nt][1]);
            float e2 = exp2f(S[nt][2]), e3 = exp2f(S[nt][3]);
            sum0 += e0 + e1; sum1 += e2 + e3;
            *(float2*)&sP[(w16 + r) * 68 + nt * 8 + 2 * q]     = make_float2(tfr(e0), tfr(e1));
            *(float2*)&sP[(w16 + r + 8) * 68 + nt * 8 + 2 * q] = make_float2(tfr(e2), tfr(e3));
        }
        sum0 += __shfl_xor_sync(0xffffffffu, sum0, 1);
        sum0 += __shfl_xor_sync(0xffffffffu, sum0, 2);
        sum1 += __shfl_xor_sync(0xffffffffu, sum1, 1);
        sum1 += __shfl_xor_sync(0xffffffffu, sum1, 2);
        l0 += sum0; l1 += sum1;
        __syncwarp();

        // O(m16 x d64) += P @ V
        {
            uint32_t padr = sPb + (uint32_t)(w16 * 68) * 4u + aof;
            uint32_t vadr = sVb + (uint32_t)(buf * 4352) * 4u + bof;
#pragma unroll
            for (int s = 0; s < 8; s++) {
                uint32_t a[4]; ldsm4(a, padr + s * 32);
#pragma unroll
                for (int j = 0; j < 4; j++) {
                    uint32_t bb[4]; ldsm4(bb, vadr + (uint32_t)(j * 16 * 68) * 4u + s * 32);
                    mma8(rO[2 * j], a, bb[0], bb[1]);
                    mma8(rO[2 * j + 1], a, bb[2], bb[3]);
                }
            }
        }
    }

    // epilogue: normalize, tf32-round, write [b][hw][c]
    const float i0 = 1.f / l0, i1 = 1.f / l1;
    const int head = p & 7, gi = p >> 3;
    const int row0 = m0 + w16 + r, row1 = row0 + 8;
    const int v0 = row0 / HW, v1 = row1 / HW;
    float* o0p = g_ao + ((gi * 4 + v0) * HW + (row0 - v0 * HW)) * CIN + head * 64;
    float* o1p = g_ao + ((gi * 4 + v1) * HW + (row1 - v1 * HW)) * CIN + head * 64;
#pragma unroll
    for (int dt = 0; dt < 8; dt++) {
        *(float2*)&o0p[dt * 8 + 2 * q] = make_float2(tfr(rO[dt][0] * i0), tfr(rO[dt][1] * i0));
        *(float2*)&o1p[dt * 8 + 2 * q] = make_float2(tfr(rO[dt][2] * i1), tfr(rO[dt][3] * i1));
    }
}

// ---------------------------------------------------------------------------
// Kernel C: proj 1x1 conv + bias. Input g_ao [b][hw][c] (tf32) -> LDSM direct.
// grid (4, 9, 8), 256 thr, M=128(o) x N=64(hw), BK=32, double-buffered.
// ---------------------------------------------------------------------------
__global__ __launch_bounds__(256, 3) void proj_mma(const float* __restrict__ bias,
                                                   float* __restrict__ out) {
    extern __shared__ float sm[];
    float* sW = sm;
    float* sX = sm + 2 * 128 * 36;
    const int tid = threadIdx.x, wp = tid >> 5, lane = tid & 31;
    const int r = lane >> 2, q = lane & 3, w16 = wp * 16;
    const int o0 = blockIdx.x * 128, hw0 = blockIdx.y * 64, b = blockIdx.z;

    const uint32_t sWb = s2u(sW), sXb = s2u(sX);
    const uint32_t aof = a_off(lane, 36), bof = b_off(lane, 36);

#define PRJ_PF(K0, BUF) {                                                        \
    _Pragma("unroll") for (int rr = 0; rr < 4; rr++) {                           \
        int f = tid + rr * 256, row = f >> 3, c4 = (f & 7) * 4;                  \
        cpa16(sWb + (uint32_t)((BUF) * 4608 + row * 36 + c4) * 4u,               \
              &g_wpr[(o0 + row) * CIN + (K0) + c4]);                             \
    }                                                                            \
    _Pragma("unroll") for (int rr = 0; rr < 2; rr++) {                           \
        int f = tid + rr * 256, row = f >> 3, c4 = (f & 7) * 4;                  \
        cpa16(sXb + (uint32_t)((BUF) * 2304 + row * 36 + c4) * 4u,               \
              &g_ao[(b * HW + hw0 + row) * CIN + (K0) + c4]);                    \
    }                                                                            \
    cpcommit(); }

    PRJ_PF(0, 0);
    float acc[8][4] = {};

    for (int kk = 0; kk < 16; kk++) {
        int buf = kk & 1;
        cpwait0();
        __syncthreads();
        if (kk + 1 < 16) PRJ_PF((kk + 1) * 32, buf ^ 1);

        uint32_t wadr = sWb + (uint32_t)(buf * 4608 + w16 * 36) * 4u + aof;
        uint32_t xadr = sXb + (uint32_t)(buf * 2304) * 4u + bof;
#pragma unroll
        for (int s = 0; s < 4; s++) {
            uint32_t a[4]; ldsm4(a, wadr + s * 32);
#pragma unroll
            for (int j = 0; j < 4; j++) {
                uint32_t bb[4]; ldsm4(bb, xadr + (uint32_t)(j * 16 * 36) * 4u + s * 32);
                mma8(acc[2 * j], a, bb[0], bb[1]);
                mma8(acc[2 * j + 1], a, bb[2], bb[3]);
            }
        }
        __syncthreads();
    }

#pragma unroll
    for (int dd = 0; dd < 2; dd++) {
        int o = o0 + w16 + r + dd * 8;
        float bv = bias[o];
#pragma unroll
        for (int nt = 0; nt < 8; nt++) {
            int hw = hw0 + nt * 8 + 2 * q;
            *(float2*)&out[(b * CIN + o) * HW + hw] =
                make_float2(acc[nt][dd * 2 + 0] + bv, acc[nt][dd * 2 + 1] + bv);
        }
    }
}

// ---------------------------------------------------------------------------
extern "C" void kernel_launch(void* const* d_in, const int* in_sizes, int n_in,
                              void* d_out, int out_size) {
    const float* x      = (const float*)d_in[0];
    const float* w_qkv  = (const float*)d_in[1];
    const float* w_proj = (const float*)d_in[2];
    const float* b_proj = (const float*)d_in[3];
    float* out = (float*)d_out;

    static int inited = 0;
    if (!inited) {
        cudaFuncSetAttribute(qkv_mma,  cudaFuncAttributeMaxDynamicSharedMemorySize, 55296);
        cudaFuncSetAttribute(flash_mma, cudaFuncAttributeMaxDynamicSharedMemorySize, 104448);
        cudaFuncSetAttribute(proj_mma, cudaFuncAttributeMaxDynamicSharedMemorySize, 55296);
        inited = 1;
    }

    cvt_k<<<3328, 256>>>((const float4*)x, (const float4*)w_qkv, (const float4*)w_proj);
    qkv_mma<<<dim3(12, 9, 8), 256, 55296>>>();
    flash_mma<<<dim3(18, 16), 256, 104448>>>();
    proj_mma<<<dim3(4, 9, 8), 256, 55296>>>(b_proj, out);
}

// round 5
// speedup vs baseline: 7.1562x; 1.8530x over previous
#include <cuda_runtime.h>
#include <cuda_fp16.h>
#include <cstdint>

#define HW     576
#define CIN    512
#define HD     64
#define NTOK   2304      // V_NUM * HW
#define NPAIR  16        // groups(2) * heads(8)
#define NB     8
#define QSCALE (0.125f * 1.4426950408889634f)   // hd^-0.5 * log2(e)

// Scratch (device globals: allocation-free rule). All fp16.
__device__ __align__(16) __half g_xt[NB * HW * CIN];     // x transposed [b][hw][c]
__device__ __align__(16) __half g_wq[3 * CIN * CIN];     // w_qkv [o][c]
__device__ __align__(16) __half g_wp[CIN * CIN];         // w_proj [o][c]
__device__ __align__(16) __half g_q[NPAIR * NTOK * HD];  // [p][n][d], scale folded
__device__ __align__(16) __half g_k[NPAIR * NTOK * HD];  // [p][n][d]
__device__ __align__(16) __half g_v[NPAIR * HD * NTOK];  // [p][d][n]
__device__ __align__(16) __half g_ao[NB * HW * CIN];     // attn out [b][hw][c]

// ---------------- helpers ----------------
__device__ __forceinline__ void mma16(float* c, const uint32_t* a, uint32_t b0, uint32_t b1) {
    asm("mma.sync.aligned.m16n8k16.row.col.f32.f16.f16.f32 "
        "{%0,%1,%2,%3}, {%4,%5,%6,%7}, {%8,%9}, {%0,%1,%2,%3};\n"
        : "+f"(c[0]), "+f"(c[1]), "+f"(c[2]), "+f"(c[3])
        : "r"(a[0]), "r"(a[1]), "r"(a[2]), "r"(a[3]), "r"(b0), "r"(b1));
}
__device__ __forceinline__ void ldsm4(uint32_t* d, uint32_t a) {
    asm volatile("ldmatrix.sync.aligned.m8n8.x4.shared.b16 {%0,%1,%2,%3}, [%4];\n"
        : "=r"(d[0]), "=r"(d[1]), "=r"(d[2]), "=r"(d[3]) : "r"(a));
}
__device__ __forceinline__ uint32_t s2u(const void* p) {
    return (uint32_t)__cvta_generic_to_shared(p);
}
__device__ __forceinline__ void cpa16(uint32_t dst, const void* src) {
    asm volatile("cp.async.cg.shared.global [%0], [%1], 16;\n" :: "r"(dst), "l"(src));
}
__device__ __forceinline__ void cpcommit() {
    asm volatile("cp.async.commit_group;\n" ::: "memory");
}
#define CPWAIT(n) asm volatile("cp.async.wait_group %0;\n" :: "n"(n) : "memory")

// fp16 LDSM lane offsets (bytes). strideB = row stride in bytes.
// A m16k16: matrices {r0-7,klo}{r8-15,klo}{r0-7,khi}{r8-15,khi}
__device__ __forceinline__ uint32_t a_off16(int lane, int strideB) {
    return (uint32_t)(((lane & 7) + ((lane >> 3) & 1) * 8) * strideB + (lane >> 4) * 16);
}
// B (rows [n][k]) x4: {n0-7,klo}{n0-7,khi}{n8-15,klo}{n8-15,khi}
__device__ __forceinline__ uint32_t b_off16(int lane, int strideB) {
    return (uint32_t)(((lane & 7) + ((lane >> 4) & 1) * 8) * strideB + ((lane >> 3) & 1) * 16);
}

#define STRB 144      // 72 halves per smem row

// ---------------------------------------------------------------------------
// Prologue 1: convert weights to fp16.
// ---------------------------------------------------------------------------
__global__ __launch_bounds__(256) void cvt_w(const float4* __restrict__ wq,
                                             const float4* __restrict__ wp) {
    int i = blockIdx.x * 256 + threadIdx.x;     // 262144 float4s
    float4 v; __half* dst;
    if (i < 196608) { v = wq[i];          dst = g_wq + i * 4; }
    else            { v = wp[i - 196608]; dst = g_wp + (i - 196608) * 4; }
    *(__half2*)dst       = __floats2half2_rn(v.x, v.y);
    *(__half2*)(dst + 2) = __floats2half2_rn(v.z, v.w);
}

// ---------------------------------------------------------------------------
// Prologue 2: transpose+convert x [b][c][hw] -> g_xt [b][hw][c] fp16.
// grid (9 hw-tiles, 8 c-tiles, 8 b), 256 thr, 64x64 tiles.
// ---------------------------------------------------------------------------
__global__ __launch_bounds__(256) void tr_x(const float* __restrict__ x) {
    __shared__ float sT[64 * 65];
    const int tid = threadIdx.x;
    const int hw0 = blockIdx.x * 64, c0 = blockIdx.y * 64, b = blockIdx.z;
#pragma unroll
    for (int rr = 0; rr < 4; rr++) {
        int f = tid + rr * 256, row = f >> 4, h4 = (f & 15) * 4;
        float4 v = *(const float4*)&x[((b * CIN) + c0 + row) * HW + hw0 + h4];
        sT[row * 65 + h4 + 0] = v.x; sT[row * 65 + h4 + 1] = v.y;
        sT[row * 65 + h4 + 2] = v.z; sT[row * 65 + h4 + 3] = v.w;
    }
    __syncthreads();
    // 256 work items: 64 hw-rows x 4 chunks of 16 channels (one pass)
    {
        int f = tid, hwr = f >> 2, cc = (f & 3) * 16;
        __half* dst = g_xt + ((b * HW) + hw0 + hwr) * CIN + c0 + cc;
#pragma unroll
        for (int j = 0; j < 8; j++)
            *(__half2*)(dst + 2 * j) =
                __floats2half2_rn(sT[(cc + 2 * j) * 65 + hwr], sT[(cc + 2 * j + 1) * 65 + hwr]);
    }
}

// ---------------------------------------------------------------------------
// Kernel A: QKV. D[m=hw 64][n=o 128] = X[hw][c] @ W[o][c]^T, K=512, BK=64.
// 8 warps (2M x 4N, warp m32 x n32). 2-stage cp.async, 1 sync/iter.
// smem: sX 2x[64][72]h, sW 2x[128][72]h = 55296 B.
// ---------------------------------------------------------------------------
__global__ __launch_bounds__(256, 3) void qkv_mma() {
    extern __shared__ __half smh[];
    const uint32_t sXb = s2u(smh);
    const uint32_t sWb = sXb + 2 * 4608 * 2;
    const int tid = threadIdx.x, wp = tid >> 5, lane = tid & 31;
    const int r = lane >> 2, q = lane & 3;
    const int wm = wp >> 2, wn = wp & 3;
    const int hw0 = blockIdx.x * 64, o0 = blockIdx.y * 128, b = blockIdx.z;
    const uint32_t aof = a_off16(lane, STRB), bof = b_off16(lane, STRB);

#define QKV_PF(K0, BUF) {                                                       \
    _Pragma("unroll") for (int rr = 0; rr < 2; rr++) {                          \
        int f = tid + rr * 256, row = f >> 3, ch = (f & 7) * 8;                 \
        cpa16(sXb + (uint32_t)((BUF) * 4608 + row * 72 + ch) * 2u,              \
              g_xt + ((b * HW) + hw0 + row) * CIN + (K0) + ch);                 \
    }                                                                           \
    _Pragma("unroll") for (int rr = 0; rr < 4; rr++) {                          \
        int f = tid + rr * 256, row = f >> 3, ch = (f & 7) * 8;                 \
        cpa16(sWb + (uint32_t)((BUF) * 9216 + row * 72 + ch) * 2u,              \
              g_wq + (o0 + row) * CIN + (K0) + ch);                             \
    }                                                                           \
    cpcommit(); }

    QKV_PF(0, 0);
    float acc[2][4][4] = {};

    for (int kk = 0; kk < 8; kk++) {
        const int buf = kk & 1;
        CPWAIT(0);
        __syncthreads();
        if (kk + 1 < 8) QKV_PF((kk + 1) * 64, buf ^ 1);

        const uint32_t xa = sXb + (uint32_t)(buf * 4608 + wm * 32 * 72) * 2u + aof;
        const uint32_t wa = sWb + (uint32_t)(buf * 9216 + wn * 32 * 72) * 2u + bof;
#pragma unroll
        for (int s = 0; s < 4; s++) {
            uint32_t aX[2][4];
            ldsm4(aX[0], xa + s * 32);
            ldsm4(aX[1], xa + 16 * STRB + s * 32);
#pragma unroll
            for (int j2 = 0; j2 < 2; j2++) {
                uint32_t bb[4]; ldsm4(bb, wa + j2 * 16 * STRB + s * 32);
#pragma unroll
                for (int mi = 0; mi < 2; mi++) {
                    mma16(acc[mi][j2 * 2],     aX[mi], bb[0], bb[1]);
                    mma16(acc[mi][j2 * 2 + 1], aX[mi], bb[2], bb[3]);
                }
            }
        }
    }

    // scatter epilogue: o = head*192 + which*64 + d ; token n = v*HW + hw
    const int g2 = b >> 2, vv = b & 3;
#pragma unroll
    for (int mi = 0; mi < 2; mi++) {
        int hwr = hw0 + wm * 32 + mi * 16 + r;
        int n0t = vv * HW + hwr, n1t = n0t + 8;
#pragma unroll
        for (int nj = 0; nj < 4; nj++) {
            int o = o0 + wn * 32 + nj * 8 + 2 * q;
            int head = o / 192, rem = o - head * 192, which = rem >> 6, d = rem & 63;
            int pp = g2 * 8 + head;
            float c0 = acc[mi][nj][0], c1 = acc[mi][nj][1];
            float c2 = acc[mi][nj][2], c3 = acc[mi][nj][3];
            if (which == 0) {
                *(__half2*)&g_q[(pp * NTOK + n0t) * HD + d] = __floats2half2_rn(c0 * QSCALE, c1 * QSCALE);
                *(__half2*)&g_q[(pp * NTOK + n1t) * HD + d] = __floats2half2_rn(c2 * QSCALE, c3 * QSCALE);
            } else if (which == 1) {
                *(__half2*)&g_k[(pp * NTOK + n0t) * HD + d] = __floats2half2_rn(c0, c1);
                *(__half2*)&g_k[(pp * NTOK + n1t) * HD + d] = __floats2half2_rn(c2, c3);
            } else {
                g_v[(pp * HD + d) * NTOK + n0t]     = __float2half_rn(c0);
                g_v[(pp * HD + d + 1) * NTOK + n0t] = __float2half_rn(c1);
                g_v[(pp * HD + d) * NTOK + n1t]     = __float2half_rn(c2);
                g_v[(pp * HD + d + 1) * NTOK + n1t] = __float2half_rn(c3);
            }
        }
    }
}

// ---------------------------------------------------------------------------
// Kernel B: flash attention fp16, max-free base-2 softmax.
// grid (18, 16), 256 thr (8 warps x m16 strips), BM=128, BN=64, 3-stage ring.
// smem: sP [128][72]h (Q staging, then P) | sK 3x[64][72]h | sV 3x[64][72]h.
// ---------------------------------------------------------------------------
__global__ __launch_bounds__(256, 2) void flash_mma() {
    extern __shared__ __half smh[];
    __half* sP = smh;
    const uint32_t sPb = s2u(sP);
    const uint32_t sKb = sPb + 128 * 72 * 2;
    const uint32_t sVb = sKb + 3 * 4608 * 2;

    const int tid = threadIdx.x, wp = tid >> 5, lane = tid & 31;
    const int r = lane >> 2, q = lane & 3, w16 = wp * 16;
    const int p = blockIdx.y, m0 = blockIdx.x * 128;

    const __half* Qb = g_q + (p * NTOK + m0) * HD;
    const __half* Kb = g_k + p * NTOK * HD;
    const __half* Vb = g_v + p * HD * NTOK;

    const uint32_t aof = a_off16(lane, STRB), bof = b_off16(lane, STRB);

#define FL_PF(N0, BUF) {                                                        \
    _Pragma("unroll") for (int rr = 0; rr < 2; rr++) {                          \
        int f = tid + rr * 256, row = f >> 3, ch = (f & 7) * 8;                 \
        cpa16(sKb + (uint32_t)((BUF) * 4608 + row * 72 + ch) * 2u,              \
              Kb + ((N0) + row) * HD + ch);                                     \
        cpa16(sVb + (uint32_t)((BUF) * 4608 + row * 72 + ch) * 2u,              \
              Vb + row * NTOK + (N0) + ch);                                     \
    }                                                                           \
    cpcommit(); }

    // stage Q, then first two K/V stages
#pragma unroll
    for (int rr = 0; rr < 4; rr++) {
        int f = tid + rr * 256, row = f >> 3, ch = (f & 7) * 8;
        cpa16(sPb + (uint32_t)(row * 72 + ch) * 2u, Qb + row * HD + ch);
    }
    cpcommit();
    FL_PF(0, 0);
    FL_PF(64, 1);

    CPWAIT(1);            // Q + stage0 ready
    __syncthreads();
    uint32_t qf[4][4];
    {
        const uint32_t qa = sPb + (uint32_t)(w16 * 72) * 2u + aof;
#pragma unroll
        for (int s = 0; s < 4; s++) ldsm4(qf[s], qa + s * 32);
    }

    float rO[8][4] = {};
    float l0 = 0.f, l1 = 0.f;

    for (int it = 0; it < 36; it++) {
        const int buf = it % 3;
        if (it) { CPWAIT(1); __syncthreads(); }
        if (it + 2 < 36) FL_PF((it + 2) * 64, (it + 2) % 3);

        // S(m16 x n64) = Q K^T  (base-2 scale folded into Q)
        float S[8][4] = {};
        {
            const uint32_t ka = sKb + (uint32_t)(buf * 4608) * 2u + bof;
#pragma unroll
            for (int s = 0; s < 4; s++)
#pragma unroll
                for (int j = 0; j < 4; j++) {
                    uint32_t bb[4]; ldsm4(bb, ka + (uint32_t)(j * 16 * STRB) + s * 32);
                    mma16(S[2 * j],     qf[s], bb[0], bb[1]);
                    mma16(S[2 * j + 1], qf[s], bb[2], bb[3]);
                }
        }

        // max-free softmax: p = exp2(S); accumulate row sums; P -> sP fp16
        float sum0 = 0.f, sum1 = 0.f;
#pragma unroll
        for (int nt = 0; nt < 8; nt++) {
            float e0 = exp2f(S[nt][0]), e1 = exp2f(S[nt][1]);
            float e2 = exp2f(S[nt][2]), e3 = exp2f(S[nt][3]);
            sum0 += e0 + e1; sum1 += e2 + e3;
            *(__half2*)&sP[(w16 + r) * 72 + nt * 8 + 2 * q]     = __floats2half2_rn(e0, e1);
            *(__half2*)&sP[(w16 + r + 8) * 72 + nt * 8 + 2 * q] = __floats2half2_rn(e2, e3);
        }
        sum0 += __shfl_xor_sync(0xffffffffu, sum0, 1);
        sum0 += __shfl_xor_sync(0xffffffffu, sum0, 2);
        sum1 += __shfl_xor_sync(0xffffffffu, sum1, 1);
        sum1 += __shfl_xor_sync(0xffffffffu, sum1, 2);
        l0 += sum0; l1 += sum1;
        __syncwarp();

        // O(m16 x d64) += P @ V
        {
            const uint32_t pa = sPb + (uint32_t)(w16 * 72) * 2u + aof;
            const uint32_t va = sVb + (uint32_t)(buf * 4608) * 2u + bof;
#pragma unroll
            for (int s = 0; s < 4; s++) {
                uint32_t pf[4]; ldsm4(pf, pa + s * 32);
#pragma unroll
                for (int j = 0; j < 4; j++) {
                    uint32_t bb[4]; ldsm4(bb, va + (uint32_t)(j * 16 * STRB) + s * 32);
                    mma16(rO[2 * j],     pf, bb[0], bb[1]);
                    mma16(rO[2 * j + 1], pf, bb[2], bb[3]);
                }
            }
        }
    }

    // epilogue: normalize, write g_ao [b][hw][c] fp16
    const float i0 = 1.f / l0, i1 = 1.f / l1;
    const int head = p & 7, gi = p >> 3;
    const int row0 = m0 + w16 + r, row1 = row0 + 8;
    const int v0 = row0 / HW, v1 = row1 / HW;
    __half* o0p = g_ao + ((gi * 4 + v0) * HW + (row0 - v0 * HW)) * CIN + head * 64;
    __half* o1p = g_ao + ((gi * 4 + v1) * HW + (row1 - v1 * HW)) * CIN + head * 64;
#pragma unroll
    for (int dt = 0; dt < 8; dt++) {
        *(__half2*)&o0p[dt * 8 + 2 * q] = __floats2half2_rn(rO[dt][0] * i0, rO[dt][1] * i0);
        *(__half2*)&o1p[dt * 8 + 2 * q] = __floats2half2_rn(rO[dt][2] * i1, rO[dt][3] * i1);
    }
}

// ---------------------------------------------------------------------------
// Kernel C: proj + bias. D[m=o 128][n=hw 64] = W[o][c] @ AO[hw][c]^T.
// 8 warps (4M x 2N, warp m32 x n32). 2-stage, 1 sync/iter. Output fp32.
// ---------------------------------------------------------------------------
__global__ __launch_bounds__(256, 3) void proj_mma(const float* __restrict__ bias,
                                                   float* __restrict__ out) {
    extern __shared__ __half smh[];
    const uint32_t sWb = s2u(smh);
    const uint32_t sBb = sWb + 2 * 9216 * 2;
    const int tid = threadIdx.x, wp = tid >> 5, lane = tid & 31;
    const int r = lane >> 2, q = lane & 3;
    const int wm = wp >> 1, wn = wp & 1;
    const int o0 = blockIdx.x * 128, hw0 = blockIdx.y * 64, b = blockIdx.z;
    const uint32_t aof = a_off16(lane, STRB), bof = b_off16(lane, STRB);

#define PRJ_PF(K0, BUF) {                                                       \
    _Pragma("unroll") for (int rr = 0; rr < 4; rr++) {                          \
        int f = tid + rr * 256, row = f >> 3, ch = (f & 7) * 8;                 \
        cpa16(sWb + (uint32_t)((BUF) * 9216 + row * 72 + ch) * 2u,              \
              g_wp + (o0 + row) * CIN + (K0) + ch);                             \
    }                                                                           \
    _Pragma("unroll") for (int rr = 0; rr < 2; rr++) {                          \
        int f = tid + rr * 256, row = f >> 3, ch = (f & 7) * 8;                 \
        cpa16(sBb + (uint32_t)((BUF) * 4608 + row * 72 + ch) * 2u,              \
              g_ao + ((b * HW) + hw0 + row) * CIN + (K0) + ch);                 \
    }                                                                           \
    cpcommit(); }

    PRJ_PF(0, 0);
    float acc[2][4][4] = {};

    for (int kk = 0; kk < 8; kk++) {
        const int buf = kk & 1;
        CPWAIT(0);
        __syncthreads();
        if (kk + 1 < 8) PRJ_PF((kk + 1) * 64, buf ^ 1);

        const uint32_t wa = sWb + (uint32_t)(buf * 9216 + wm * 32 * 72) * 2u + aof;
        const uint32_t xa = sBb + (uint32_t)(buf * 4608 + wn * 32 * 72) * 2u + bof;
#pragma unroll
        for (int s = 0; s < 4; s++) {
            uint32_t aW[2][4];
            ldsm4(aW[0], wa + s * 32);
            ldsm4(aW[1], wa + 16 * STRB + s * 32);
#pragma unroll
            for (int j2 = 0; j2 < 2; j2++) {
                uint32_t bb[4]; ldsm4(bb, xa + j2 * 16 * STRB + s * 32);
#pragma unroll
                for (int mi = 0; mi < 2; mi++) {
                    mma16(acc[mi][j2 * 2],     aW[mi], bb[0], bb[1]);
                    mma16(acc[mi][j2 * 2 + 1], aW[mi], bb[2], bb[3]);
                }
            }
        }
    }

#pragma unroll
    for (int mi = 0; mi < 2; mi++) {
        int o_r = o0 + wm * 32 + mi * 16 + r;
        float bv0 = bias[o_r], bv1 = bias[o_r + 8];
#pragma unroll
        for (int nj = 0; nj < 4; nj++) {
            int hw = hw0 + wn * 32 + nj * 8 + 2 * q;
            *(float2*)&out[(b * CIN + o_r) * HW + hw] =
                make_float2(acc[mi][nj][0] + bv0, acc[mi][nj][1] + bv0);
            *(float2*)&out[(b * CIN + o_r + 8) * HW + hw] =
                make_float2(acc[mi][nj][2] + bv1, acc[mi][nj][3] + bv1);
        }
    }
}

// ---------------------------------------------------------------------------
extern "C" void kernel_launch(void* const* d_in, const int* in_sizes, int n_in,
                              void* d_out, int out_size) {
    const float* x      = (const float*)d_in[0];
    const float* w_qkv  = (const float*)d_in[1];
    const float* w_proj = (const float*)d_in[2];
    const float* b_proj = (const float*)d_in[3];
    float* out = (float*)d_out;

    cudaFuncSetAttribute(qkv_mma,   cudaFuncAttributeMaxDynamicSharedMemorySize, 55296);
    cudaFuncSetAttribute(flash_mma, cudaFuncAttributeMaxDynamicSharedMemorySize, 73728);
    cudaFuncSetAttribute(proj_mma,  cudaFuncAttributeMaxDynamicSharedMemorySize, 55296);

    cvt_w<<<1024, 256>>>((const float4*)w_qkv, (const float4*)w_proj);
    tr_x<<<dim3(9, 8, 8), 256>>>(x);
    qkv_mma<<<dim3(9, 12, 8), 256, 55296>>>();
    flash_mma<<<dim3(18, 16), 256, 73728>>>();
    proj_mma<<<dim3(4, 9, 8), 256, 55296>>>(b_proj, out);
}